// round 1
// baseline (speedup 1.0000x reference)
#include <cuda_runtime.h>
#include <math.h>

// Problem constants
#define Bb 8
#define Ss_ 512     // S (temporal length)
#define Mm 8        // M agents
#define Dd 512
#define Hh 8
#define DH 64
#define SSq 16      // static query count
#define KSn 16      // static key count
#define SMf 4096    // S*M
#define NKEY (SMf + KSn)   // 4112
#define SCALE 0.125f

#define TROWS (Bb*Ss_*Mm)  // 32768
#define SROWS (Bb*SSq)     // 128

// Scratch (device globals — no allocation allowed in kernel_launch)
__device__ float g_qt[(size_t)TROWS*Dd];
__device__ float g_kt[(size_t)TROWS*Dd];
__device__ float g_vt[(size_t)TROWS*Dd];
__device__ float g_qkvt[(size_t)TROWS*Dd];
__device__ float g_qs[(size_t)SROWS*Dd];
__device__ float g_ks[(size_t)SROWS*Dd];
__device__ float g_vs[(size_t)SROWS*Dd];
__device__ float g_qkvs[(size_t)SROWS*Dd];

// ---------------------------------------------------------------------------
// GEMM: C[rows, 512] = A[rows,512] @ W[512,512] + bias
// BM=BN=128, BK=16, 256 threads, 8x8 per thread. rows % 128 == 0.
// ---------------------------------------------------------------------------
__global__ __launch_bounds__(256) void gemm_bias_kernel(
    const float* __restrict__ A, const float* __restrict__ W,
    const float* __restrict__ bias, float* __restrict__ C)
{
    __shared__ __align__(16) float As[16][128];
    __shared__ __align__(16) float Bs[16][128];

    const int tid  = threadIdx.x;
    const int brow = blockIdx.y * 128;
    const int bcol = blockIdx.x * 128;
    const int ty = tid >> 4;   // 0..15
    const int tx = tid & 15;   // 0..15

    float acc[8][8];
#pragma unroll
    for (int i = 0; i < 8; i++)
#pragma unroll
        for (int j = 0; j < 8; j++) acc[i][j] = 0.f;

    for (int k0 = 0; k0 < Dd; k0 += 16) {
        // Load A tile (128x16): 512 float4 loads, 2 per thread
#pragma unroll
        for (int i = 0; i < 2; i++) {
            int f  = tid + i * 256;
            int r  = f >> 2;         // 0..127
            int kq = f & 3;          // float4 index within BK
            float4 v = *(const float4*)(A + (size_t)(brow + r) * Dd + k0 + kq * 4);
            As[kq*4+0][r] = v.x; As[kq*4+1][r] = v.y;
            As[kq*4+2][r] = v.z; As[kq*4+3][r] = v.w;
        }
        // Load B tile (16x128): rows contiguous, perfectly coalesced
#pragma unroll
        for (int i = 0; i < 2; i++) {
            int f  = tid + i * 256;
            int kk = f >> 5;         // 0..15
            int cq = f & 31;         // 0..31
            float4 v = *(const float4*)(W + (size_t)(k0 + kk) * Dd + bcol + cq * 4);
            *(float4*)&Bs[kk][cq*4] = v;
        }
        __syncthreads();
#pragma unroll
        for (int kk = 0; kk < 16; kk++) {
            float4 a0 = *(const float4*)&As[kk][ty*8];
            float4 a1 = *(const float4*)&As[kk][ty*8+4];
            float4 b0 = *(const float4*)&Bs[kk][tx*8];
            float4 b1 = *(const float4*)&Bs[kk][tx*8+4];
            float ar[8] = {a0.x,a0.y,a0.z,a0.w,a1.x,a1.y,a1.z,a1.w};
            float br[8] = {b0.x,b0.y,b0.z,b0.w,b1.x,b1.y,b1.z,b1.w};
#pragma unroll
            for (int i = 0; i < 8; i++)
#pragma unroll
                for (int j = 0; j < 8; j++) acc[i][j] += ar[i]*br[j];
        }
        __syncthreads();
    }

#pragma unroll
    for (int i = 0; i < 8; i++) {
        int r = brow + ty*8 + i;
#pragma unroll
        for (int j = 0; j < 8; j += 4) {
            int c = bcol + tx*8 + j;
            float4 o;
            o.x = acc[i][j]   + bias[c];
            o.y = acc[i][j+1] + bias[c+1];
            o.z = acc[i][j+2] + bias[c+2];
            o.w = acc[i][j+3] + bias[c+3];
            *(float4*)(C + (size_t)r * Dd + c) = o;
        }
    }
}

// ---------------------------------------------------------------------------
// Temporal attention: one block per (b,h,s), 64 threads (thread = column d)
// ---------------------------------------------------------------------------
__global__ __launch_bounds__(64) void temporal_attn_kernel(
    const float* __restrict__ Qt, const float* __restrict__ Kt,
    const float* __restrict__ Vt, const float* __restrict__ Ksp,
    const float* __restrict__ Vsp, const int* __restrict__ mt,
    const int* __restrict__ ms, float* __restrict__ w_t,
    float* __restrict__ qkvt)
{
    const int idx = blockIdx.x;
    const int s = idx % Ss_;
    const int h = (idx / Ss_) % Hh;
    const int b = idx / (Ss_ * Hh);
    const int d = threadIdx.x;

    __shared__ float q[Mm][DH+1], k[Mm][DH+1], v[Mm][DH+1];
    __shared__ float ks[KSn][DH+1], vs[KSn][DH+1];
    __shared__ float sc[Mm][Mm+KSn];

    const size_t base_t = ((size_t)(b*Ss_ + s) * Mm) * Dd + (size_t)h * DH;
#pragma unroll
    for (int m = 0; m < Mm; m++) {
        q[m][d] = Qt[base_t + (size_t)m*Dd + d];
        k[m][d] = Kt[base_t + (size_t)m*Dd + d];
        v[m][d] = Vt[base_t + (size_t)m*Dd + d];
    }
    const size_t base_s = (size_t)b*KSn*Dd + (size_t)h*DH;
#pragma unroll
    for (int n = 0; n < KSn; n++) {
        ks[n][d] = Ksp[base_s + (size_t)n*Dd + d];
        vs[n][d] = Vsp[base_s + (size_t)n*Dd + d];
    }
    __syncthreads();

    // 8*24 = 192 scores, 3 per thread
    for (int e = d; e < Mm*(Mm+KSn); e += 64) {
        int m = e / (Mm+KSn), n = e % (Mm+KSn);
        const float* kp = (n < Mm) ? k[n] : ks[n-Mm];
        float acc = 0.f;
#pragma unroll
        for (int kk = 0; kk < DH; kk++) acc += q[m][kk] * kp[kk];
        int maskv = (n < Mm) ? mt[(b*Ss_+s)*Mm + n] : ms[b*KSn + (n-Mm)];
        sc[m][n] = acc * SCALE + (maskv ? 0.f : -1e30f);
    }
    __syncthreads();

    if (d < Mm) {
        const int m = d;
        float mx = -1e38f;
#pragma unroll
        for (int n = 0; n < Mm+KSn; n++) mx = fmaxf(mx, sc[m][n]);
        float sum = 0.f;
#pragma unroll
        for (int n = 0; n < Mm+KSn; n++) { float e = __expf(sc[m][n]-mx); sc[m][n] = e; sum += e; }
        float inv = 1.f / sum;
        size_t wbase = ((((size_t)(b*Hh+h)*Ss_ + s) * Mm) + m) * (Mm+KSn);
#pragma unroll
        for (int n = 0; n < Mm+KSn; n++) { float p = sc[m][n]*inv; sc[m][n] = p; w_t[wbase+n] = p; }
    }
    __syncthreads();

#pragma unroll
    for (int m = 0; m < Mm; m++) {
        float acc = 0.f;
#pragma unroll
        for (int n = 0; n < Mm; n++)  acc += sc[m][n] * v[n][d];
#pragma unroll
        for (int n = 0; n < KSn; n++) acc += sc[m][Mm+n] * vs[n][d];
        qkvt[base_t + (size_t)m*Dd + d] = acc;
    }
}

// ---------------------------------------------------------------------------
// Static attention: one block per (b,h,q), 256 threads
// ---------------------------------------------------------------------------
__global__ __launch_bounds__(256) void static_attn_kernel(
    const float* __restrict__ Qs, const float* __restrict__ Ktf,
    const float* __restrict__ Vtf, const float* __restrict__ Ksp,
    const float* __restrict__ Vsp, const int* __restrict__ mt,
    const int* __restrict__ ms, float* __restrict__ w_s,
    float* __restrict__ qkvs)
{
    const int qi = blockIdx.x % SSq;
    const int h  = (blockIdx.x / SSq) % Hh;
    const int b  = blockIdx.x / (SSq * Hh);
    const int tid = threadIdx.x;

    __shared__ float p[NKEY];
    __shared__ __align__(16) float qrow[DH];
    __shared__ float red[256];
    __shared__ float pout[4][DH];

    if (tid < DH) qrow[tid] = Qs[((size_t)(b*SSq+qi))*Dd + (size_t)h*DH + tid];
    __syncthreads();

    const float4* q4 = (const float4*)qrow;
    float lmax = -1e38f;
    for (int n = tid; n < NKEY; n += 256) {
        const float* kp = (n < SMf)
            ? Ktf + ((size_t)(b*SMf + n))*Dd + (size_t)h*DH
            : Ksp + ((size_t)(b*KSn + n - SMf))*Dd + (size_t)h*DH;
        const float4* kp4 = (const float4*)kp;
        float acc = 0.f;
#pragma unroll
        for (int kk = 0; kk < DH/4; kk++) {
            float4 a = q4[kk]; float4 bv = kp4[kk];
            acc += a.x*bv.x + a.y*bv.y + a.z*bv.z + a.w*bv.w;
        }
        int maskv = (n < SMf) ? mt[b*SMf + n] : ms[b*KSn + n - SMf];
        float sv = acc * SCALE + (maskv ? 0.f : -1e30f);
        p[n] = sv;
        lmax = fmaxf(lmax, sv);
    }
    red[tid] = lmax; __syncthreads();
    for (int off = 128; off > 0; off >>= 1) {
        if (tid < off) red[tid] = fmaxf(red[tid], red[tid+off]);
        __syncthreads();
    }
    const float mx = red[0]; __syncthreads();

    float lsum = 0.f;
    for (int n = tid; n < NKEY; n += 256) {
        float e = __expf(p[n] - mx); p[n] = e; lsum += e;
    }
    red[tid] = lsum; __syncthreads();
    for (int off = 128; off > 0; off >>= 1) {
        if (tid < off) red[tid] += red[tid+off];
        __syncthreads();
    }
    const float inv = 1.f / red[0]; __syncthreads();

    const size_t wbase = (((size_t)(b*Hh+h)*SSq) + qi) * (size_t)NKEY;
    for (int n = tid; n < NKEY; n += 256) {
        float pn = p[n] * inv;
        p[n] = pn;
        w_s[wbase + n] = pn;
    }
    __syncthreads();

    // weighted V sum, split across 4 chunks of 64 threads
    const int chunk = tid / DH;   // 0..3
    const int d = tid % DH;
    float acc = 0.f;
    for (int n = chunk; n < NKEY; n += 4) {
        const float* vp = (n < SMf)
            ? Vtf + ((size_t)(b*SMf + n))*Dd + (size_t)h*DH
            : Vsp + ((size_t)(b*KSn + n - SMf))*Dd + (size_t)h*DH;
        acc += p[n] * vp[d];
    }
    pout[chunk][d] = acc; __syncthreads();
    if (tid < DH) {
        float o = pout[0][tid] + pout[1][tid] + pout[2][tid] + pout[3][tid];
        qkvs[((size_t)(b*SSq+qi))*Dd + (size_t)h*DH + tid] = o;
    }
}

// ---------------------------------------------------------------------------
extern "C" void kernel_launch(void* const* d_in, const int* in_sizes, int n_in,
                              void* d_out, int out_size)
{
    (void)in_sizes; (void)n_in; (void)out_size;
    const float* q_t = (const float*)d_in[0];
    const float* k_t = (const float*)d_in[1];
    const float* v_t = (const float*)d_in[2];
    const float* q_s = (const float*)d_in[3];
    const float* k_s = (const float*)d_in[4];
    const float* v_s = (const float*)d_in[5];
    const int*   m_t = (const int*)d_in[6];
    const int*   m_s = (const int*)d_in[7];
    const float* Wq = (const float*)d_in[8];
    const float* bq = (const float*)d_in[9];
    const float* Wk = (const float*)d_in[10];
    const float* bk = (const float*)d_in[11];
    const float* Wv = (const float*)d_in[12];
    const float* bv = (const float*)d_in[13];
    const float* Wo = (const float*)d_in[14];
    const float* bo = (const float*)d_in[15];

    float* out   = (float*)d_out;
    float* out_t = out;                                                  // [B,S,M,D]
    float* w_t   = out_t + (size_t)Bb*Ss_*Mm*Dd;                         // [B,H,S,M,24]
    float* out_s = w_t + (size_t)Bb*Hh*Ss_*Mm*(Mm+KSn);                  // [B,Ss,D]
    float* w_s   = out_s + (size_t)Bb*SSq*Dd;                            // [B,H,Ss,4112]

    float *p_qt, *p_kt, *p_vt, *p_qkvt, *p_qs, *p_ks, *p_vs, *p_qkvs;
    cudaGetSymbolAddress((void**)&p_qt,   g_qt);
    cudaGetSymbolAddress((void**)&p_kt,   g_kt);
    cudaGetSymbolAddress((void**)&p_vt,   g_vt);
    cudaGetSymbolAddress((void**)&p_qkvt, g_qkvt);
    cudaGetSymbolAddress((void**)&p_qs,   g_qs);
    cudaGetSymbolAddress((void**)&p_ks,   g_ks);
    cudaGetSymbolAddress((void**)&p_vs,   g_vs);
    cudaGetSymbolAddress((void**)&p_qkvs, g_qkvs);

    const dim3 gbig(Dd/128, TROWS/128);   // 4 x 256
    const dim3 gsmall(Dd/128, SROWS/128); // 4 x 1

    // Projections
    gemm_bias_kernel<<<gbig,   256>>>(q_t, Wq, bq, p_qt);
    gemm_bias_kernel<<<gbig,   256>>>(k_t, Wk, bk, p_kt);
    gemm_bias_kernel<<<gbig,   256>>>(v_t, Wv, bv, p_vt);
    gemm_bias_kernel<<<gsmall, 256>>>(q_s, Wq, bq, p_qs);
    gemm_bias_kernel<<<gsmall, 256>>>(k_s, Wk, bk, p_ks);
    gemm_bias_kernel<<<gsmall, 256>>>(v_s, Wv, bv, p_vs);

    // Attention
    temporal_attn_kernel<<<Bb*Hh*Ss_, 64>>>(p_qt, p_kt, p_vt, p_ks, p_vs,
                                            m_t, m_s, w_t, p_qkvt);
    static_attn_kernel<<<Bb*Hh*SSq, 256>>>(p_qs, p_kt, p_vt, p_ks, p_vs,
                                           m_t, m_s, w_s, p_qkvs);

    // Output projections
    gemm_bias_kernel<<<gbig,   256>>>(p_qkvt, Wo, bo, out_t);
    gemm_bias_kernel<<<gsmall, 256>>>(p_qkvs, Wo, bo, out_s);
}

// round 3
// speedup vs baseline: 1.8307x; 1.8307x over previous
#include <cuda_runtime.h>
#include <cuda_bf16.h>
#include <cstdint>
#include <math.h>

typedef __nv_bfloat16 bf16;

// Problem constants
#define Bb 8
#define Ss_ 512
#define Mm 8
#define Dd 512
#define Hh 8
#define DH 64
#define SSq 16
#define KSn 16
#define SMf 4096
#define NKEY (SMf + KSn)
#define SCALE 0.125f

#define TROWS (Bb*Ss_*Mm)  // 32768
#define SROWS (Bb*SSq)     // 128

// ---------------------------------------------------------------------------
// Scratch (device globals — no allocation allowed)
// ---------------------------------------------------------------------------
__device__ float g_qt[(size_t)TROWS*Dd];
__device__ float g_kt[(size_t)TROWS*Dd];
__device__ float g_vt[(size_t)TROWS*Dd];
__device__ float g_qkvt[(size_t)TROWS*Dd];
__device__ float g_qs[(size_t)SROWS*Dd];
__device__ float g_ks[(size_t)SROWS*Dd];
__device__ float g_vs[(size_t)SROWS*Dd];
__device__ float g_qkvs[(size_t)SROWS*Dd];
// Transposed + split weights: [N=512][K=512] bf16, hi and lo, 4 matrices
__device__ bf16 g_wth[4][(size_t)Dd*Dd];
__device__ bf16 g_wtl[4][(size_t)Dd*Dd];

// ---------------------------------------------------------------------------
__device__ __forceinline__ uint32_t bf2u(__nv_bfloat162 v) {
    return *reinterpret_cast<uint32_t*>(&v);
}
__device__ __forceinline__ void split2(float x, float y, uint32_t& h, uint32_t& l) {
    __nv_bfloat162 H = __floats2bfloat162_rn(x, y);
    float hx = __bfloat162float(H.x), hy = __bfloat162float(H.y);
    __nv_bfloat162 L = __floats2bfloat162_rn(x - hx, y - hy);
    h = bf2u(H); l = bf2u(L);
}

__device__ __forceinline__ void mma16816(float* c,
    uint32_t a0, uint32_t a1, uint32_t a2, uint32_t a3,
    uint32_t b0, uint32_t b1)
{
    asm volatile(
        "mma.sync.aligned.m16n8k16.row.col.f32.bf16.bf16.f32 "
        "{%0,%1,%2,%3}, {%4,%5,%6,%7}, {%8,%9}, {%0,%1,%2,%3};"
        : "+f"(c[0]), "+f"(c[1]), "+f"(c[2]), "+f"(c[3])
        : "r"(a0), "r"(a1), "r"(a2), "r"(a3), "r"(b0), "r"(b1));
}

// ---------------------------------------------------------------------------
// Weight transpose + split: WT[n][k] = W[k][n] in bf16 hi/lo. grid (16,16,4)
// ---------------------------------------------------------------------------
struct WArgs { const float* W[4]; bf16* Wh[4]; bf16* Wl[4]; };

__global__ __launch_bounds__(256) void wsplit_kernel(WArgs a) {
    const int z = blockIdx.z;
    const float* W = a.W[z];
    bf16* Wh = a.Wh[z];
    bf16* Wl = a.Wl[z];
    __shared__ float t[32][33];
    const int x0 = blockIdx.x * 32, y0 = blockIdx.y * 32;
    const int tx = threadIdx.x, ty = threadIdx.y;
#pragma unroll
    for (int i = ty; i < 32; i += 8)
        t[i][tx] = W[(size_t)(y0 + i) * Dd + x0 + tx];
    __syncthreads();
#pragma unroll
    for (int i = ty; i < 32; i += 8) {
        float v = t[tx][i];                 // = W[y0+tx][x0+i]
        bf16 h = __float2bfloat16(v);
        bf16 l = __float2bfloat16(v - __bfloat162float(h));
        size_t o = (size_t)(x0 + i) * Dd + y0 + tx;
        Wh[o] = h; Wl[o] = l;
    }
}

// ---------------------------------------------------------------------------
// MMA GEMM: C[rows,512] = A[rows,512] @ W[512,512] + bias (fp32 in/out)
// 2-term bf16 split emulation via mma.sync m16n8k16.
// CTA tile 128x128, BK=32, 8 warps as 4(M) x 2(N) -> warp tile 32x64.
// Batched over blockIdx.z.
// ---------------------------------------------------------------------------
struct GB { const float* A; const bf16* Wh; const bf16* Wl;
            const float* bias; float* C; int rows; };
struct GBatch { GB g[6]; };

#define BK 32
#define KPAD 40   // bf16 elems per smem row; 80B stride -> conflict-free frag loads

__global__ __launch_bounds__(256, 2) void mma_gemm(GBatch batch) {
    const GB a = batch.g[blockIdx.z];
    const int brow = blockIdx.y * 128;
    if (brow >= a.rows) return;
    const int bcol = blockIdx.x * 128;

    __shared__ bf16 sAh[128][KPAD];
    __shared__ bf16 sAl[128][KPAD];
    __shared__ bf16 sWh[128][KPAD];
    __shared__ bf16 sWl[128][KPAD];

    const int tid = threadIdx.x;
    const int wid = tid >> 5, lane = tid & 31;
    const int warpM = wid & 3;       // 0..3 -> 32-row slab
    const int warpN = wid >> 2;      // 0..1 -> 64-col slab
    const int ra = lane >> 2;        // groupID
    const int tk = (lane & 3) * 2;   // k pair offset

    float acc[2][8][4];
#pragma unroll
    for (int mi = 0; mi < 2; mi++)
#pragma unroll
        for (int ni = 0; ni < 8; ni++)
#pragma unroll
            for (int j = 0; j < 4; j++) acc[mi][ni][j] = 0.f;

    for (int k0 = 0; k0 < Dd; k0 += BK) {
        // ---- stage A (fp32 -> bf16 hi/lo split) ----
#pragma unroll
        for (int i = 0; i < 4; i++) {
            int idx = tid + i * 256;          // 0..1023
            int r  = idx >> 3;                // 0..127
            int c4 = idx & 7;                 // float4 col 0..7
            float4 v = *(const float4*)(a.A + (size_t)(brow + r) * Dd + k0 + c4 * 4);
            uint32_t h0, l0, h1, l1;
            split2(v.x, v.y, h0, l0);
            split2(v.z, v.w, h1, l1);
            *(uint2*)&sAh[r][c4 * 4] = make_uint2(h0, h1);
            *(uint2*)&sAl[r][c4 * 4] = make_uint2(l0, l1);
        }
        // ---- stage W hi/lo (pre-split bf16, [N][K]) ----
#pragma unroll
        for (int i = 0; i < 2; i++) {
            int idx = tid + i * 256;          // 0..511
            int r = idx >> 2;                 // 0..127
            int q = idx & 3;                  // uint4 col
            uint4 vh = *(const uint4*)(a.Wh + (size_t)(bcol + r) * Dd + k0 + q * 8);
            uint4 vl = *(const uint4*)(a.Wl + (size_t)(bcol + r) * Dd + k0 + q * 8);
            *(uint4*)&sWh[r][q * 8] = vh;
            *(uint4*)&sWl[r][q * 8] = vl;
        }
        __syncthreads();

        // ---- compute: 2 k16 steps ----
#pragma unroll
        for (int ks = 0; ks < 2; ks++) {
            const int kb = ks * 16 + tk;
            uint32_t ah[2][4], al[2][4];
#pragma unroll
            for (int mi = 0; mi < 2; mi++) {
                int r0 = warpM * 32 + mi * 16 + ra;
                const uint32_t* ph0 = (const uint32_t*)&sAh[r0][kb];
                const uint32_t* ph1 = (const uint32_t*)&sAh[r0 + 8][kb];
                ah[mi][0] = ph0[0]; ah[mi][1] = ph1[0];
                ah[mi][2] = ph0[4]; ah[mi][3] = ph1[4];
                const uint32_t* pl0 = (const uint32_t*)&sAl[r0][kb];
                const uint32_t* pl1 = (const uint32_t*)&sAl[r0 + 8][kb];
                al[mi][0] = pl0[0]; al[mi][1] = pl1[0];
                al[mi][2] = pl0[4]; al[mi][3] = pl1[4];
            }
#pragma unroll
            for (int ni = 0; ni < 8; ni++) {
                int n = warpN * 64 + ni * 8 + ra;
                const uint32_t* pwh = (const uint32_t*)&sWh[n][kb];
                const uint32_t* pwl = (const uint32_t*)&sWl[n][kb];
                uint32_t wh0 = pwh[0], wh1 = pwh[4];
                uint32_t wl0 = pwl[0], wl1 = pwl[4];
#pragma unroll
                for (int mi = 0; mi < 2; mi++) {
                    mma16816(acc[mi][ni], ah[mi][0], ah[mi][1], ah[mi][2], ah[mi][3], wh0, wh1);
                    mma16816(acc[mi][ni], ah[mi][0], ah[mi][1], ah[mi][2], ah[mi][3], wl0, wl1);
                    mma16816(acc[mi][ni], al[mi][0], al[mi][1], al[mi][2], al[mi][3], wh0, wh1);
                }
            }
        }
        __syncthreads();
    }

    // ---- epilogue ----
#pragma unroll
    for (int mi = 0; mi < 2; mi++) {
        int row0 = brow + warpM * 32 + mi * 16 + ra;
#pragma unroll
        for (int ni = 0; ni < 8; ni++) {
            int col = bcol + warpN * 64 + ni * 8 + tk;
            float bx = a.bias[col], by = a.bias[col + 1];
            float2 o0 = make_float2(acc[mi][ni][0] + bx, acc[mi][ni][1] + by);
            float2 o1 = make_float2(acc[mi][ni][2] + bx, acc[mi][ni][3] + by);
            *(float2*)(a.C + (size_t)row0 * Dd + col) = o0;
            *(float2*)(a.C + (size_t)(row0 + 8) * Dd + col) = o1;
        }
    }
}

// ---------------------------------------------------------------------------
// Temporal attention (unchanged — known correct)
// ---------------------------------------------------------------------------
__global__ __launch_bounds__(64) void temporal_attn_kernel(
    const float* __restrict__ Qt, const float* __restrict__ Kt,
    const float* __restrict__ Vt, const float* __restrict__ Ksp,
    const float* __restrict__ Vsp, const int* __restrict__ mt,
    const int* __restrict__ ms, float* __restrict__ w_t,
    float* __restrict__ qkvt)
{
    const int idx = blockIdx.x;
    const int s = idx % Ss_;
    const int h = (idx / Ss_) % Hh;
    const int b = idx / (Ss_ * Hh);
    const int d = threadIdx.x;

    __shared__ float q[Mm][DH+1], k[Mm][DH+1], v[Mm][DH+1];
    __shared__ float ks[KSn][DH+1], vs[KSn][DH+1];
    __shared__ float sc[Mm][Mm+KSn];

    const size_t base_t = ((size_t)(b*Ss_ + s) * Mm) * Dd + (size_t)h * DH;
#pragma unroll
    for (int m = 0; m < Mm; m++) {
        q[m][d] = Qt[base_t + (size_t)m*Dd + d];
        k[m][d] = Kt[base_t + (size_t)m*Dd + d];
        v[m][d] = Vt[base_t + (size_t)m*Dd + d];
    }
    const size_t base_s = (size_t)b*KSn*Dd + (size_t)h*DH;
#pragma unroll
    for (int n = 0; n < KSn; n++) {
        ks[n][d] = Ksp[base_s + (size_t)n*Dd + d];
        vs[n][d] = Vsp[base_s + (size_t)n*Dd + d];
    }
    __syncthreads();

    for (int e = d; e < Mm*(Mm+KSn); e += 64) {
        int m = e / (Mm+KSn), n = e % (Mm+KSn);
        const float* kp = (n < Mm) ? k[n] : ks[n-Mm];
        float acc = 0.f;
#pragma unroll
        for (int kk = 0; kk < DH; kk++) acc += q[m][kk] * kp[kk];
        int maskv = (n < Mm) ? mt[(b*Ss_+s)*Mm + n] : ms[b*KSn + (n-Mm)];
        sc[m][n] = acc * SCALE + (maskv ? 0.f : -1e30f);
    }
    __syncthreads();

    if (d < Mm) {
        const int m = d;
        float mx = -1e38f;
#pragma unroll
        for (int n = 0; n < Mm+KSn; n++) mx = fmaxf(mx, sc[m][n]);
        float sum = 0.f;
#pragma unroll
        for (int n = 0; n < Mm+KSn; n++) { float e = __expf(sc[m][n]-mx); sc[m][n] = e; sum += e; }
        float inv = 1.f / sum;
        size_t wbase = ((((size_t)(b*Hh+h)*Ss_ + s) * Mm) + m) * (Mm+KSn);
#pragma unroll
        for (int n = 0; n < Mm+KSn; n++) { float p = sc[m][n]*inv; sc[m][n] = p; w_t[wbase+n] = p; }
    }
    __syncthreads();

#pragma unroll
    for (int m = 0; m < Mm; m++) {
        float acc = 0.f;
#pragma unroll
        for (int n = 0; n < Mm; n++)  acc += sc[m][n] * v[n][d];
#pragma unroll
        for (int n = 0; n < KSn; n++) acc += sc[m][Mm+n] * vs[n][d];
        qkvt[base_t + (size_t)m*Dd + d] = acc;
    }
}

// ---------------------------------------------------------------------------
// Static attention (unchanged — known correct)
// ---------------------------------------------------------------------------
__global__ __launch_bounds__(256) void static_attn_kernel(
    const float* __restrict__ Qs, const float* __restrict__ Ktf,
    const float* __restrict__ Vtf, const float* __restrict__ Ksp,
    const float* __restrict__ Vsp, const int* __restrict__ mt,
    const int* __restrict__ ms, float* __restrict__ w_s,
    float* __restrict__ qkvs)
{
    const int qi = blockIdx.x % SSq;
    const int h  = (blockIdx.x / SSq) % Hh;
    const int b  = blockIdx.x / (SSq * Hh);
    const int tid = threadIdx.x;

    __shared__ float p[NKEY];
    __shared__ __align__(16) float qrow[DH];
    __shared__ float red[256];
    __shared__ float pout[4][DH];

    if (tid < DH) qrow[tid] = Qs[((size_t)(b*SSq+qi))*Dd + (size_t)h*DH + tid];
    __syncthreads();

    const float4* q4 = (const float4*)qrow;
    float lmax = -1e38f;
    for (int n = tid; n < NKEY; n += 256) {
        const float* kp = (n < SMf)
            ? Ktf + ((size_t)(b*SMf + n))*Dd + (size_t)h*DH
            : Ksp + ((size_t)(b*KSn + n - SMf))*Dd + (size_t)h*DH;
        const float4* kp4 = (const float4*)kp;
        float acc = 0.f;
#pragma unroll
        for (int kk = 0; kk < DH/4; kk++) {
            float4 a = q4[kk]; float4 bv = kp4[kk];
            acc += a.x*bv.x + a.y*bv.y + a.z*bv.z + a.w*bv.w;
        }
        int maskv = (n < SMf) ? mt[b*SMf + n] : ms[b*KSn + n - SMf];
        float sv = acc * SCALE + (maskv ? 0.f : -1e30f);
        p[n] = sv;
        lmax = fmaxf(lmax, sv);
    }
    red[tid] = lmax; __syncthreads();
    for (int off = 128; off > 0; off >>= 1) {
        if (tid < off) red[tid] = fmaxf(red[tid], red[tid+off]);
        __syncthreads();
    }
    const float mx = red[0]; __syncthreads();

    float lsum = 0.f;
    for (int n = tid; n < NKEY; n += 256) {
        float e = __expf(p[n] - mx); p[n] = e; lsum += e;
    }
    red[tid] = lsum; __syncthreads();
    for (int off = 128; off > 0; off >>= 1) {
        if (tid < off) red[tid] += red[tid+off];
        __syncthreads();
    }
    const float inv = 1.f / red[0]; __syncthreads();

    const size_t wbase = (((size_t)(b*Hh+h)*SSq) + qi) * (size_t)NKEY;
    for (int n = tid; n < NKEY; n += 256) {
        float pn = p[n] * inv;
        p[n] = pn;
        w_s[wbase + n] = pn;
    }
    __syncthreads();

    const int chunk = tid / DH;
    const int d = tid % DH;
    float acc = 0.f;
    for (int n = chunk; n < NKEY; n += 4) {
        const float* vp = (n < SMf)
            ? Vtf + ((size_t)(b*SMf + n))*Dd + (size_t)h*DH
            : Vsp + ((size_t)(b*KSn + n - SMf))*Dd + (size_t)h*DH;
        acc += p[n] * vp[d];
    }
    pout[chunk][d] = acc; __syncthreads();
    if (tid < DH) {
        float o = pout[0][tid] + pout[1][tid] + pout[2][tid] + pout[3][tid];
        qkvs[((size_t)(b*SSq+qi))*Dd + (size_t)h*DH + tid] = o;
    }
}

// ---------------------------------------------------------------------------
extern "C" void kernel_launch(void* const* d_in, const int* in_sizes, int n_in,
                              void* d_out, int out_size)
{
    (void)in_sizes; (void)n_in; (void)out_size;
    const float* q_t = (const float*)d_in[0];
    const float* k_t = (const float*)d_in[1];
    const float* v_t = (const float*)d_in[2];
    const float* q_s = (const float*)d_in[3];
    const float* k_s = (const float*)d_in[4];
    const float* v_s = (const float*)d_in[5];
    const int*   m_t = (const int*)d_in[6];
    const int*   m_s = (const int*)d_in[7];
    const float* Wq = (const float*)d_in[8];
    const float* bq = (const float*)d_in[9];
    const float* Wk = (const float*)d_in[10];
    const float* bk = (const float*)d_in[11];
    const float* Wv = (const float*)d_in[12];
    const float* bv = (const float*)d_in[13];
    const float* Wo = (const float*)d_in[14];
    const float* bo = (const float*)d_in[15];

    float* out   = (float*)d_out;
    float* out_t = out;
    float* w_t   = out_t + (size_t)Bb*Ss_*Mm*Dd;
    float* out_s = w_t + (size_t)Bb*Hh*Ss_*Mm*(Mm+KSn);
    float* w_s   = out_s + (size_t)Bb*SSq*Dd;

    float *p_qt, *p_kt, *p_vt, *p_qkvt, *p_qs, *p_ks, *p_vs, *p_qkvs;
    bf16 *p_wth, *p_wtl;
    cudaGetSymbolAddress((void**)&p_qt,   g_qt);
    cudaGetSymbolAddress((void**)&p_kt,   g_kt);
    cudaGetSymbolAddress((void**)&p_vt,   g_vt);
    cudaGetSymbolAddress((void**)&p_qkvt, g_qkvt);
    cudaGetSymbolAddress((void**)&p_qs,   g_qs);
    cudaGetSymbolAddress((void**)&p_ks,   g_ks);
    cudaGetSymbolAddress((void**)&p_vs,   g_vs);
    cudaGetSymbolAddress((void**)&p_qkvs, g_qkvs);
    cudaGetSymbolAddress((void**)&p_wth,  g_wth);
    cudaGetSymbolAddress((void**)&p_wtl,  g_wtl);

    const size_t WSZ = (size_t)Dd * Dd;
    bf16* wqh = p_wth + 0*WSZ; bf16* wql = p_wtl + 0*WSZ;
    bf16* wkh = p_wth + 1*WSZ; bf16* wkl = p_wtl + 1*WSZ;
    bf16* wvh = p_wth + 2*WSZ; bf16* wvl = p_wtl + 2*WSZ;
    bf16* woh = p_wth + 3*WSZ; bf16* wol = p_wtl + 3*WSZ;

    // 1) weight transpose+split
    WArgs wa;
    wa.W[0] = Wq; wa.Wh[0] = wqh; wa.Wl[0] = wql;
    wa.W[1] = Wk; wa.Wh[1] = wkh; wa.Wl[1] = wkl;
    wa.W[2] = Wv; wa.Wh[2] = wvh; wa.Wl[2] = wvl;
    wa.W[3] = Wo; wa.Wh[3] = woh; wa.Wl[3] = wol;
    wsplit_kernel<<<dim3(16,16,4), dim3(32,8)>>>(wa);

    // 2) all six input projections in one batched launch
    GBatch pb;
    pb.g[0] = { q_t, wqh, wql, bq, p_qt, TROWS };
    pb.g[1] = { k_t, wkh, wkl, bk, p_kt, TROWS };
    pb.g[2] = { v_t, wvh, wvl, bv, p_vt, TROWS };
    pb.g[3] = { q_s, wqh, wql, bq, p_qs, SROWS };
    pb.g[4] = { k_s, wkh, wkl, bk, p_ks, SROWS };
    pb.g[5] = { v_s, wvh, wvl, bv, p_vs, SROWS };
    mma_gemm<<<dim3(4, 256, 6), 256>>>(pb);

    // 3) attention
    temporal_attn_kernel<<<Bb*Hh*Ss_, 64>>>(p_qt, p_kt, p_vt, p_ks, p_vs,
                                            m_t, m_s, w_t, p_qkvt);
    static_attn_kernel<<<Bb*Hh*SSq, 256>>>(p_qs, p_kt, p_vt, p_ks, p_vs,
                                           m_t, m_s, w_s, p_qkvs);

    // 4) output projections (batched)
    GBatch ob;
    ob.g[0] = { p_qkvt, woh, wol, bo, out_t, TROWS };
    ob.g[1] = { p_qkvs, woh, wol, bo, out_s, SROWS };
    ob.g[2] = ob.g[0]; ob.g[3] = ob.g[0]; ob.g[4] = ob.g[0]; ob.g[5] = ob.g[0];
    mma_gemm<<<dim3(4, 256, 2), 256>>>(ob);
}